// round 14
// baseline (speedup 1.0000x reference)
#include <cuda_runtime.h>
#include <cuda_bf16.h>
#include <math.h>
#include <cstdint>

// Problem constants
#define Bn 4
#define Tn 256
#define Un 64
#define U1 65
#define Vn 1024
#define Fn 80
#define Hn 512
#define Jn 512
#define NROWS (Bn*Tn*U1)   // 66560 = 520*128
#define NEGF (-1e30f)

// ---------------- scratch (static __device__, allocation-free) ----------------
__device__ float g_Wcomb[Fn*Jn];                 // W_enc @ W_jenc (80x512)
__device__ float g_e  [Bn*Tn*Jn];                // (1024, 512)
__device__ float g_dec[Bn*U1*Hn];                // (260, 512)
__device__ float g_d  [Bn*U1*Jn];                // (260, 512)
__device__ __nv_bfloat16 g_Wt[(size_t)Vn*Jn];    // W_out^T bf16, [V][J] K-major
__device__ float g_blank[NROWS];                 // [b][t][u]
__device__ float g_lbl[Bn*Tn*Un];                // [b][t][u]

__device__ __forceinline__ uint32_t s2u(const void* p){
    uint32_t a;
    asm("{ .reg .u64 t; cvta.to.shared.u64 t, %1; cvt.u32.u64 %0, t; }" : "=r"(a) : "l"(p));
    return a;
}
__device__ __forceinline__ float tanhap(float x){
    float y; asm("tanh.approx.f32 %0, %1;" : "=f"(y) : "f"(x)); return y;
}
// fast logaddexp (MUFU-based; abs err ~1e-6)
__device__ __forceinline__ float laef(float a, float b){
    float m = fmaxf(a,b);
    float d = fabsf(a-b);
    return m + __logf(1.f + __expf(-d));
}
// per-row swizzle bits for 64B rows: flips 16B-chunk index (bits 4,5) by row bits 1,2
#define XBITS(r) ((((uint32_t)(r))&6u)<<3)

// ---------------- 32x32-tile SGEMM body (device fn, 256 threads) ----------------
__device__ void gemm32_dev(const float* __restrict__ A, const float* __restrict__ B,
                           float* __restrict__ C, int M, int N, int K, int bx, int by,
                           float* As /*[32*33]*/, float* Bs /*[32*33]*/){
    int tid = threadIdx.x;
    int tx = tid & 15, ty = tid >> 4;
    int rowBase = by*32, colBase = bx*32;
    float acc[2][2] = {};
    for(int k0=0;k0<K;k0+=32){
        #pragma unroll
        for(int i=0;i<4;i++){
            int idx = i*256+tid;
            int m = idx>>5, k = idx&31;
            int gm = rowBase+m, gk = k0+k;
            As[m*33+k] = (gm<M && gk<K) ? A[(size_t)gm*K+gk] : 0.f;
            int kb = idx>>5, n = idx&31;
            int gkb = k0+kb, gn = colBase+n;
            Bs[kb*33+n] = (gkb<K && gn<N) ? B[(size_t)gkb*N+gn] : 0.f;
        }
        __syncthreads();
        #pragma unroll
        for(int kk=0;kk<32;kk++){
            float a0 = As[(ty*2+0)*33+kk], a1 = As[(ty*2+1)*33+kk];
            float b0 = Bs[kk*33+tx*2+0], b1 = Bs[kk*33+tx*2+1];
            acc[0][0] = fmaf(a0,b0,acc[0][0]);
            acc[0][1] = fmaf(a0,b1,acc[0][1]);
            acc[1][0] = fmaf(a1,b0,acc[1][0]);
            acc[1][1] = fmaf(a1,b1,acc[1][1]);
        }
        __syncthreads();
    }
    #pragma unroll
    for(int i=0;i<2;i++){
        int gm = rowBase+ty*2+i;
        if(gm<M)
            #pragma unroll
            for(int j=0;j<2;j++){
                int gn = colBase+tx*2+j;
                if(gn<N) C[(size_t)gm*N+gn]=acc[i][j];
            }
    }
}

// ---------------- prep1: Wcomb GEMM + gather_dec + wtrans in one launch ----------------
__global__ __launch_bounds__(256) void prep1(const float* __restrict__ W_enc,
                                             const float* __restrict__ W_jenc,
                                             const float* __restrict__ emb,
                                             const int* __restrict__ targets,
                                             const float* __restrict__ W_out,
                                             float* __restrict__ out){
    __shared__ float sh[2*32*33];
    int bid = blockIdx.x, tid = threadIdx.x;
    if(bid < 48){
        gemm32_dev(W_enc, W_jenc, g_Wcomb, Fn, Jn, Hn, bid&15, bid>>4, sh, sh+32*33);
    } else if(bid < 308){
        if(bid==48 && tid==0) out[0] = 0.f;
        int row = bid - 48;                 // 0..259 = b*65+u
        int b = row / U1, u = row - b*U1;
        int tok = (u==0) ? 0 : targets[b*Un + (u-1)];
        const float* src = emb + (size_t)tok*Hn;
        float* dst = g_dec + (size_t)row*Hn;
        #pragma unroll
        for(int i=0;i<2;i++) dst[tid + i*256] = src[tid + i*256];
    } else {
        int idx = bid - 308;                // 512 tiles: 32 v-tiles x 16 j-tiles
        int v0 = (idx & 31)*32, j0 = (idx >> 5)*32;
        float (*t)[33] = (float(*)[33])sh;
        int tx = tid & 31, ty = tid >> 5;   // 32 x 8
        for(int i=ty;i<32;i+=8)
            t[i][tx] = W_out[(size_t)(j0+i)*Vn + v0 + tx];
        __syncthreads();
        for(int i=ty;i<32;i+=8)
            g_Wt[(size_t)(v0+i)*Jn + j0 + tx] = __float2bfloat16(t[tx][i]);
    }
}

// ---------------- prep2: e-GEMM + d-GEMM in one launch ----------------
__global__ __launch_bounds__(256) void prep2(const float* __restrict__ inputs,
                                             const float* __restrict__ W_jdec){
    __shared__ float sh[2*32*33];
    int bid = blockIdx.x;
    if(bid < 512){
        gemm32_dev(inputs, g_Wcomb, g_e, Bn*Tn, Jn, Fn, bid&15, bid>>4, sh, sh+32*33);
    } else {
        int idx = bid - 512;                // 144: 9 row x 16 col tiles
        gemm32_dev(g_dec, W_jdec, g_d, Bn*U1, Jn, Hn, idx&15, idx>>4, sh, sh+32*33);
    }
}

// ================= fused joint kernel (u-major tiling + dead-CTA skip) =================
// Grid 520 = 65 u x 4 b x 2 t-halves. CTA: 128 t-rows (single u,b) x 1024 cols.
// Early exit if u > tgt_lens[b] or t0 >= in_lens[b]  (rows never read by DP).
#define ABYTES (16*128*64)            // 131072
#define BRING  (8*128*64)             // 65536
#define SOFFB  (ABYTES + BRING)       // 196608
#define DBOFF  (SOFFB + 3584)         // d+bj row (512 f32)
#define BIG_SMEM (DBOFF + 2048)       // 202240
__global__ void __launch_bounds__(256) big_fused(const float* __restrict__ bout,
                                                 const float* __restrict__ bj,
                                                 const int* __restrict__ targets,
                                                 const int* __restrict__ in_lens,
                                                 const int* __restrict__ tgt_lens){
    int u    = blockIdx.x >> 3;          // 0..64
    int sub  = blockIdx.x & 7;
    int b    = sub >> 1;                 // 0..3
    int t0   = (sub & 1) * 128;
    if(u > tgt_lens[b]) return;          // dead column band
    if(t0 >= in_lens[b]) return;         // dead time band

    extern __shared__ char sm[];
    uint32_t sA = s2u(sm);
    uint32_t sB = sA + ABYTES;
    float* pm  = (float*)(sm + SOFFB);          // [2][128]
    float* ps  = pm + 256;                      // [2][128]
    float* pvt = ps + 256;                      // [2][128]
    float* pv0 = pvt + 256;                     // [128]
    float* db  = (float*)(sm + DBOFF);          // d_u + bj (512)

    int tid = threadIdx.x, wid = tid>>5, lane = tid&31;
    int g = lane>>2, tg = lane&3;
    int warp_m = wid & 3, warp_n = wid >> 2;    // 4 x 2
    int tgt = (u < Un) ? targets[b*Un + u] : -1;

    // ---- stage d_u + bj ----
    {
        const float* drow = g_d + (size_t)(b*U1+u)*Jn;
        #pragma unroll
        for(int i=0;i<2;i++){
            int k = tid + i*256;
            db[k] = drow[k] + bj[k];
        }
    }
    __syncthreads();

    // ---- prologue: H = tanh(e[bt] + db) -> bf16 into A smem; warp owns 16 rows ----
    {
        int r0 = wid*16;
        #pragma unroll
        for(int rr=0;rr<16;rr++){
            int r = r0 + rr;
            int bt = b*Tn + t0 + r;
            const float4* ep = (const float4*)(g_e + (size_t)bt*Jn);
            const float4* dp = (const float4*)db;
            uint32_t xr = XBITS(r);
            uint32_t colsw = (((uint32_t)(lane&7))*8u) ^ xr;
            #pragma unroll
            for(int i=0;i<4;i++){
                int k = i*128 + lane*4;
                float4 e4 = ep[k>>2], d4 = dp[k>>2];
                __nv_bfloat162 o0 = __floats2bfloat162_rn(tanhap(e4.x+d4.x), tanhap(e4.y+d4.y));
                __nv_bfloat162 o1 = __floats2bfloat162_rn(tanhap(e4.z+d4.z), tanhap(e4.w+d4.w));
                int kt = i*4 + (lane>>3);
                uint32_t addr = sA + (uint32_t)kt*8192 + (uint32_t)r*64 + colsw;
                uint32_t w0 = *(unsigned*)&o0, w1 = *(unsigned*)&o1;
                asm volatile("st.shared.v2.b32 [%0], {%1,%2};" :: "r"(addr), "r"(w0), "r"(w1));
            }
        }
    }

    // per-slot local rows (slot = mt*2 + half)
    int rows4[4];
    #pragma unroll
    for(int mt=0;mt<2;mt++)
        #pragma unroll
        for(int half=0;half<2;half++)
            rows4[mt*2+half] = warp_m*32 + mt*16 + half*8 + g;

    // ldmatrix swizzled offsets within a kt/buffer tile, both ks variants
    uint32_t aOff2[2][2];
    #pragma unroll
    for(int mt=0;mt<2;mt++){
        int r = warp_m*32 + mt*16 + (lane&7) + ((lane>>3)&1)*8;
        uint32_t off16 = ((lane>>4)&1)*16;
        #pragma unroll
        for(int ks=0;ks<2;ks++)
            aOff2[mt][ks] = (uint32_t)r*64 + ((off16 | (ks<<5)) ^ XBITS(r));
    }
    uint32_t bOff2[4][2];
    #pragma unroll
    for(int j=0;j<4;j++){
        int n = warp_n*64 + j*16 + (lane&7) + ((lane>>4)&1)*8;
        uint32_t off16 = ((lane>>3)&1)*16;
        #pragma unroll
        for(int ks=0;ks<2;ks++)
            bOff2[j][ks] = (uint32_t)n*64 + ((off16 | (ks<<5)) ^ XBITS(n));
    }

    float m4[4] = {-3.4e38f,-3.4e38f,-3.4e38f,-3.4e38f};
    float s4[4] = {0.f,0.f,0.f,0.f};
    float vt4[4] = {-3.4e38f,-3.4e38f,-3.4e38f,-3.4e38f};
    float v04[4] = {0.f,0.f,0.f,0.f};

    int brow = tid>>1, bc0 = (tid&1)*2;   // 128 rows x 2 x 16B per thread
    uint32_t bst0 = (uint32_t)brow*64 + (((uint32_t)bc0*16u)       ^ XBITS(brow));
    uint32_t bst1 = (uint32_t)brow*64 + (((uint32_t)bc0*16u + 16u) ^ XBITS(brow));
    #define LOADB(buf, stp) do{ \
        unsigned long long p = __cvta_generic_to_global( \
            (const char*)g_Wt + ((size_t)(((stp)>>4)*128 + brow))*1024 + ((stp)&15)*64 + bc0*16); \
        uint32_t dbase = sB + (uint32_t)(buf)*8192; \
        asm volatile("cp.async.cg.shared.global [%0], [%1], 16;" :: "r"(dbase + bst0), "l"(p)); \
        asm volatile("cp.async.cg.shared.global [%0], [%1], 16;" :: "r"(dbase + bst1), "l"(p+16)); \
    }while(0)

    // prefetch steps 0..3 (one commit group each)
    LOADB(0,0); asm volatile("cp.async.commit_group;");
    LOADB(1,1); asm volatile("cp.async.commit_group;");
    LOADB(2,2); asm volatile("cp.async.commit_group;");
    LOADB(3,3); asm volatile("cp.async.commit_group;");

    float acc[2][8][4];
    #pragma unroll
    for(int mt=0;mt<2;mt++)
        #pragma unroll
        for(int nt=0;nt<8;nt++)
            #pragma unroll
            for(int c=0;c<4;c++) acc[mt][nt][c]=0.f;

    for(int it=0; it<64; it++){
        int p0 = 2*it;
        if(p0+4 < 128){ LOADB((p0+4)&7, p0+4); }
        asm volatile("cp.async.commit_group;");
        if(p0+5 < 128){ LOADB((p0+5)&7, p0+5); }
        asm volatile("cp.async.commit_group;");
        asm volatile("cp.async.wait_group 4;");
        __syncthreads();

        #pragma unroll
        for(int half2=0; half2<2; half2++){
            int stp = p0 + half2;
            uint32_t aoff = sA + (uint32_t)(stp & 15)*8192;
            uint32_t boff = sB + (uint32_t)(stp & 7)*8192;
            #pragma unroll
            for(int ks=0;ks<2;ks++){
                uint32_t af[2][4];
                #pragma unroll
                for(int mt=0;mt<2;mt++)
                    asm volatile("ldmatrix.sync.aligned.m8n8.x4.shared.b16 {%0,%1,%2,%3}, [%4];"
                        : "=r"(af[mt][0]),"=r"(af[mt][1]),"=r"(af[mt][2]),"=r"(af[mt][3])
                        : "r"(aoff + aOff2[mt][ks]));
                uint32_t bf[8][2];
                #pragma unroll
                for(int j=0;j<4;j++){
                    uint32_t b0,b1,b2,b3;
                    asm volatile("ldmatrix.sync.aligned.m8n8.x4.shared.b16 {%0,%1,%2,%3}, [%4];"
                        : "=r"(b0),"=r"(b1),"=r"(b2),"=r"(b3)
                        : "r"(boff + bOff2[j][ks]));
                    bf[2*j][0]=b0; bf[2*j][1]=b1; bf[2*j+1][0]=b2; bf[2*j+1][1]=b3;
                }
                #pragma unroll
                for(int mt=0;mt<2;mt++)
                    #pragma unroll
                    for(int nt=0;nt<8;nt++)
                        asm volatile(
                            "mma.sync.aligned.m16n8k16.row.col.f32.bf16.bf16.f32 "
                            "{%0,%1,%2,%3}, {%4,%5,%6,%7}, {%8,%9}, {%0,%1,%2,%3};"
                            : "+f"(acc[mt][nt][0]), "+f"(acc[mt][nt][1]),
                              "+f"(acc[mt][nt][2]), "+f"(acc[mt][nt][3])
                            : "r"(af[mt][0]),"r"(af[mt][1]),"r"(af[mt][2]),"r"(af[mt][3]),
                              "r"(bf[nt][0]),"r"(bf[nt][1]));
            }
        }

        if(((p0+1) & 15) == 15){
            int nch = (p0+1) >> 4;
            int colw = nch*128 + warp_n*64;
            float br0[8], br1[8];
            #pragma unroll
            for(int nt=0;nt<8;nt++){
                br0[nt] = __ldg(&bout[colw + nt*8 + tg*2]);
                br1[nt] = __ldg(&bout[colw + nt*8 + tg*2 + 1]);
            }
            #pragma unroll
            for(int mt=0;mt<2;mt++){
                #pragma unroll
                for(int half=0;half<2;half++){
                    int slot = mt*2+half;
                    float v[16];
                    float cm = -3.4e38f;
                    #pragma unroll
                    for(int nt=0;nt<8;nt++){
                        v[nt*2]   = acc[mt][nt][half*2]   + br0[nt];
                        v[nt*2+1] = acc[mt][nt][half*2+1] + br1[nt];
                        cm = fmaxf(cm, fmaxf(v[nt*2], v[nt*2+1]));
                    }
                    float nm = fmaxf(m4[slot], cm);
                    float s = s4[slot]*__expf(m4[slot]-nm);
                    #pragma unroll
                    for(int nt=0;nt<8;nt++){
                        s += __expf(v[nt*2]-nm);
                        s += __expf(v[nt*2+1]-nm);
                        int c0 = colw + nt*8 + tg*2;
                        if(c0   == tgt) vt4[slot] = v[nt*2];
                        if(c0+1 == tgt) vt4[slot] = v[nt*2+1];
                    }
                    m4[slot] = nm; s4[slot] = s;
                    if(nch==0 && warp_n==0 && tg==0) v04[slot] = v[0];
                }
            }
            #pragma unroll
            for(int mt=0;mt<2;mt++)
                #pragma unroll
                for(int nt=0;nt<8;nt++)
                    #pragma unroll
                    for(int c=0;c<4;c++) acc[mt][nt][c]=0.f;
        }
    }
    #undef LOADB

    // ---- cross-quad + cross-warp_n combine ----
    #pragma unroll
    for(int slot=0;slot<4;slot++){
        #pragma unroll
        for(int o=1;o<4;o<<=1){
            float om = __shfl_xor_sync(0xffffffffu, m4[slot], o);
            float os = __shfl_xor_sync(0xffffffffu, s4[slot], o);
            float ov = __shfl_xor_sync(0xffffffffu, vt4[slot], o);
            float nm = fmaxf(m4[slot], om);
            s4[slot] = s4[slot]*__expf(m4[slot]-nm) + os*__expf(om-nm);
            m4[slot] = nm;
            vt4[slot] = fmaxf(vt4[slot], ov);
        }
        if(tg==0){
            int rl = rows4[slot];
            pm [warp_n*128 + rl] = m4[slot];
            ps [warp_n*128 + rl] = s4[slot];
            pvt[warp_n*128 + rl] = vt4[slot];
            if(warp_n==0) pv0[rl] = v04[slot];
        }
    }
    __syncthreads();
    if(tid < 128){
        int r = tid;
        int t = t0 + r;
        float m0 = pm[r], m1 = pm[128+r];
        float nm = fmaxf(m0, m1);
        float s = ps[r]*__expf(m0-nm) + ps[128+r]*__expf(m1-nm);
        float lse = nm + logf(s);
        g_blank[b*(Tn*U1) + t*U1 + u] = pv0[r] - lse;
        if(u < Un && u < tgt_lens[b]){
            float vt = fmaxf(pvt[r], pvt[128+r]);
            g_lbl[b*(Tn*Un) + t*Un + u] = vt - lse;
        }
    }
}

// ---------------- RNN-T forward DP: single-warp register wavefront ----------------
// Lane l owns u=2l (lo), u=2l+1 (hi); lane 31 also owns u=64 (ex).
// Diagonal n cells use only diagonal n-1 values: own regs + shfl_up of hi.
// No barriers in the 320-step loop.
#define DP_SMEM ((Tn*U1 + Tn*Un)*4)   // 132096 bytes
__device__ __forceinline__ float dp_cell(int n, int u, int uf, float pu, float pum1,
                                         const float* sb, const float* sl){
    int t = n - u;
    if(t < 0 || t >= Tn) return pu;          // not started / past end (unused)
    if(t == 0 && u == 0) return 0.f;
    if(t == 0) return (u <= uf) ? (pum1 + sl[u-1]) : NEGF;
    if(u == 0) return pu + sb[(t-1)*U1];
    if(u > uf) return NEGF;
    return laef(pu + sb[(t-1)*U1 + u], pum1 + sl[t*Un + (u-1)]);
}
__global__ void dp_kernel(const int* __restrict__ in_lens, const int* __restrict__ tgt_lens,
                          float* __restrict__ out){
    extern __shared__ float smf[];
    float* s_blank = smf;              // Tn*U1
    float* s_lbl   = smf + Tn*U1;      // Tn*Un
    int b = blockIdx.x;
    for(int i=threadIdx.x;i<Tn*U1;i+=blockDim.x) s_blank[i] = g_blank[b*Tn*U1 + i];
    for(int i=threadIdx.x;i<Tn*Un;i+=blockDim.x) s_lbl[i]   = g_lbl[b*Tn*Un + i];
    __syncthreads();
    if(threadIdx.x >= 32) return;      // warp 0 only from here (no more barriers)

    int l = threadIdx.x;
    int tl = in_lens[b]-1;
    int uf = tgt_lens[b];
    int lim = tl + uf;
    int u_lo = 2*l, u_hi = 2*l+1;
    float lo = NEGF, hi = NEGF, ex = NEGF;
    float fin = NEGF;
    for(int n=0;n<=lim;n++){
        float hprev = __shfl_up_sync(0xffffffffu, hi, 1);   // prev[u_lo-1]
        float olo = lo, ohi = hi, oex = ex;
        lo = dp_cell(n, u_lo, uf, olo, hprev, s_blank, s_lbl);
        hi = dp_cell(n, u_hi, uf, ohi, olo,   s_blank, s_lbl);
        if(l == 31) ex = dp_cell(n, 64, uf, oex, ohi, s_blank, s_lbl);
        // capture final cell alpha(tl, uf) + blank(tl, uf)
        if(n == tl + uf){
            float av = (uf == u_lo) ? lo : ((uf == u_hi) ? hi : ((uf == 64 && l == 31) ? ex : NEGF));
            if(uf == u_lo || uf == u_hi || (uf == 64 && l == 31))
                fin = av + s_blank[tl*U1 + uf];
        }
    }
    // one lane holds fin; others NEGF
    #pragma unroll
    for(int o=16;o>=1;o>>=1) fin = fmaxf(fin, __shfl_xor_sync(0xffffffffu, fin, o));
    if(l == 0) atomicAdd(out, -fin * (1.0f/Bn));
}

// ---------------- launch ----------------
extern "C" void kernel_launch(void* const* d_in, const int* in_sizes, int n_in,
                              void* d_out, int out_size){
    (void)in_sizes; (void)n_in; (void)out_size;
    const float* inputs  = (const float*)d_in[0];
    const float* W_enc   = (const float*)d_in[1];
    const float* emb     = (const float*)d_in[2];
    const float* W_jenc  = (const float*)d_in[3];
    const float* W_jdec  = (const float*)d_in[4];
    const float* b_j     = (const float*)d_in[5];
    const float* W_out   = (const float*)d_in[6];
    const float* b_out   = (const float*)d_in[7];
    const int*   targets = (const int*)d_in[8];
    const int*   in_lens = (const int*)d_in[9];
    const int*   tgt_lens= (const int*)d_in[10];
    float* out = (float*)d_out;

    cudaFuncSetAttribute(big_fused, cudaFuncAttributeMaxDynamicSharedMemorySize, BIG_SMEM);
    cudaFuncSetAttribute(dp_kernel, cudaFuncAttributeMaxDynamicSharedMemorySize, DP_SMEM);

    prep1<<<820, 256>>>(W_enc, W_jenc, emb, targets, W_out, out);
    prep2<<<656, 256>>>(inputs, W_jdec);
    big_fused<<<U1*Bn*2, 256, BIG_SMEM>>>(b_out, b_j, targets, in_lens, tgt_lens);
    dp_kernel<<<Bn, 128, DP_SMEM>>>(in_lens, tgt_lens, out);
}

// round 15
// speedup vs baseline: 1.0006x; 1.0006x over previous
#include <cuda_runtime.h>
#include <cuda_bf16.h>
#include <math.h>
#include <cstdint>

// Problem constants
#define Bn 4
#define Tn 256
#define Un 64
#define U1 65
#define Vn 1024
#define Fn 80
#define Hn 512
#define Jn 512
#define NROWS (Bn*Tn*U1)   // 66560 = 520*128
#define NEGF (-1e30f)

// ---------------- scratch (static __device__, allocation-free) ----------------
__device__ float g_Wcomb[Fn*Jn];                 // W_enc @ W_jenc (80x512)
__device__ float g_e  [Bn*Tn*Jn];                // (1024, 512)
__device__ float g_dec[Bn*U1*Hn];                // (260, 512)
__device__ float g_d  [Bn*U1*Jn];                // (260, 512)
__device__ __nv_bfloat16 g_Wt[(size_t)Vn*Jn];    // W_out^T bf16, [V][J] K-major
__device__ float g_blank[NROWS];                 // [b][t][u]
__device__ float g_lbl[Bn*Tn*Un];                // [b][t][u]

__device__ __forceinline__ uint32_t s2u(const void* p){
    uint32_t a;
    asm("{ .reg .u64 t; cvta.to.shared.u64 t, %1; cvt.u32.u64 %0, t; }" : "=r"(a) : "l"(p));
    return a;
}
__device__ __forceinline__ float tanhap(float x){
    float y; asm("tanh.approx.f32 %0, %1;" : "=f"(y) : "f"(x)); return y;
}
// fast logaddexp (MUFU-based; abs err ~1e-6)
__device__ __forceinline__ float laef(float a, float b){
    float m = fmaxf(a,b);
    float d = fabsf(a-b);
    return m + __logf(1.f + __expf(-d));
}
// per-row swizzle bits for 64B rows: flips 16B-chunk index (bits 4,5) by row bits 1,2
#define XBITS(r) ((((uint32_t)(r))&6u)<<3)

// ---------------- 32x32-tile SGEMM body (device fn, 256 threads) ----------------
__device__ void gemm32_dev(const float* __restrict__ A, const float* __restrict__ B,
                           float* __restrict__ C, int M, int N, int K, int bx, int by,
                           float* As /*[32*33]*/, float* Bs /*[32*33]*/){
    int tid = threadIdx.x;
    int tx = tid & 15, ty = tid >> 4;
    int rowBase = by*32, colBase = bx*32;
    float acc[2][2] = {};
    for(int k0=0;k0<K;k0+=32){
        #pragma unroll
        for(int i=0;i<4;i++){
            int idx = i*256+tid;
            int m = idx>>5, k = idx&31;
            int gm = rowBase+m, gk = k0+k;
            As[m*33+k] = (gm<M && gk<K) ? A[(size_t)gm*K+gk] : 0.f;
            int kb = idx>>5, n = idx&31;
            int gkb = k0+kb, gn = colBase+n;
            Bs[kb*33+n] = (gkb<K && gn<N) ? B[(size_t)gkb*N+gn] : 0.f;
        }
        __syncthreads();
        #pragma unroll
        for(int kk=0;kk<32;kk++){
            float a0 = As[(ty*2+0)*33+kk], a1 = As[(ty*2+1)*33+kk];
            float b0 = Bs[kk*33+tx*2+0], b1 = Bs[kk*33+tx*2+1];
            acc[0][0] = fmaf(a0,b0,acc[0][0]);
            acc[0][1] = fmaf(a0,b1,acc[0][1]);
            acc[1][0] = fmaf(a1,b0,acc[1][0]);
            acc[1][1] = fmaf(a1,b1,acc[1][1]);
        }
        __syncthreads();
    }
    #pragma unroll
    for(int i=0;i<2;i++){
        int gm = rowBase+ty*2+i;
        if(gm<M)
            #pragma unroll
            for(int j=0;j<2;j++){
                int gn = colBase+tx*2+j;
                if(gn<N) C[(size_t)gm*N+gn]=acc[i][j];
            }
    }
}

// ---------------- prep1: Wcomb GEMM + gather_dec + wtrans in one launch ----------------
__global__ __launch_bounds__(256) void prep1(const float* __restrict__ W_enc,
                                             const float* __restrict__ W_jenc,
                                             const float* __restrict__ emb,
                                             const int* __restrict__ targets,
                                             const float* __restrict__ W_out,
                                             float* __restrict__ out){
    __shared__ float sh[2*32*33];
    int bid = blockIdx.x, tid = threadIdx.x;
    if(bid < 48){
        gemm32_dev(W_enc, W_jenc, g_Wcomb, Fn, Jn, Hn, bid&15, bid>>4, sh, sh+32*33);
    } else if(bid < 308){
        if(bid==48 && tid==0) out[0] = 0.f;
        int row = bid - 48;                 // 0..259 = b*65+u
        int b = row / U1, u = row - b*U1;
        int tok = (u==0) ? 0 : targets[b*Un + (u-1)];
        const float* src = emb + (size_t)tok*Hn;
        float* dst = g_dec + (size_t)row*Hn;
        #pragma unroll
        for(int i=0;i<2;i++) dst[tid + i*256] = src[tid + i*256];
    } else {
        int idx = bid - 308;                // 512 tiles: 32 v-tiles x 16 j-tiles
        int v0 = (idx & 31)*32, j0 = (idx >> 5)*32;
        float (*t)[33] = (float(*)[33])sh;
        int tx = tid & 31, ty = tid >> 5;   // 32 x 8
        for(int i=ty;i<32;i+=8)
            t[i][tx] = W_out[(size_t)(j0+i)*Vn + v0 + tx];
        __syncthreads();
        for(int i=ty;i<32;i+=8)
            g_Wt[(size_t)(v0+i)*Jn + j0 + tx] = __float2bfloat16(t[tx][i]);
    }
}

// ---------------- prep2: e-GEMM + d-GEMM in one launch ----------------
__global__ __launch_bounds__(256) void prep2(const float* __restrict__ inputs,
                                             const float* __restrict__ W_jdec){
    __shared__ float sh[2*32*33];
    int bid = blockIdx.x;
    if(bid < 512){
        gemm32_dev(inputs, g_Wcomb, g_e, Bn*Tn, Jn, Fn, bid&15, bid>>4, sh, sh+32*33);
    } else {
        int idx = bid - 512;                // 144: 9 row x 16 col tiles
        gemm32_dev(g_dec, W_jdec, g_d, Bn*U1, Jn, Hn, idx&15, idx>>4, sh, sh+32*33);
    }
}

// ================= fused joint kernel (u-major tiling + dead-CTA skip) =================
// Grid 520 = 65 u x 4 b x 2 t-halves. CTA: 128 t-rows (single u,b) x 1024 cols.
// Early exit if u > tgt_lens[b] or t0 >= in_lens[b]  (rows never read by DP).
#define ABYTES (16*128*64)            // 131072
#define BRING  (8*128*64)             // 65536
#define SOFFB  (ABYTES + BRING)       // 196608
#define DBOFF  (SOFFB + 3584)         // d+bj row (512 f32)
#define BIG_SMEM (DBOFF + 2048)       // 202240
__global__ void __launch_bounds__(256) big_fused(const float* __restrict__ bout,
                                                 const float* __restrict__ bj,
                                                 const int* __restrict__ targets,
                                                 const int* __restrict__ in_lens,
                                                 const int* __restrict__ tgt_lens){
    int u    = blockIdx.x >> 3;          // 0..64
    int sub  = blockIdx.x & 7;
    int b    = sub >> 1;                 // 0..3
    int t0   = (sub & 1) * 128;
    if(u > tgt_lens[b]) return;          // dead column band
    if(t0 >= in_lens[b]) return;         // dead time band

    extern __shared__ char sm[];
    uint32_t sA = s2u(sm);
    uint32_t sB = sA + ABYTES;
    float* pm  = (float*)(sm + SOFFB);          // [2][128]
    float* ps  = pm + 256;                      // [2][128]
    float* pvt = ps + 256;                      // [2][128]
    float* pv0 = pvt + 256;                     // [128]
    float* db  = (float*)(sm + DBOFF);          // d_u + bj (512)

    int tid = threadIdx.x, wid = tid>>5, lane = tid&31;
    int g = lane>>2, tg = lane&3;
    int warp_m = wid & 3, warp_n = wid >> 2;    // 4 x 2
    int tgt = (u < Un) ? targets[b*Un + u] : -1;

    // ---- stage d_u + bj ----
    {
        const float* drow = g_d + (size_t)(b*U1+u)*Jn;
        #pragma unroll
        for(int i=0;i<2;i++){
            int k = tid + i*256;
            db[k] = drow[k] + bj[k];
        }
    }
    __syncthreads();

    // ---- prologue: H = tanh(e[bt] + db) -> bf16 into A smem; warp owns 16 rows ----
    {
        int r0 = wid*16;
        #pragma unroll
        for(int rr=0;rr<16;rr++){
            int r = r0 + rr;
            int bt = b*Tn + t0 + r;
            const float4* ep = (const float4*)(g_e + (size_t)bt*Jn);
            const float4* dp = (const float4*)db;
            uint32_t xr = XBITS(r);
            uint32_t colsw = (((uint32_t)(lane&7))*8u) ^ xr;
            #pragma unroll
            for(int i=0;i<4;i++){
                int k = i*128 + lane*4;
                float4 e4 = ep[k>>2], d4 = dp[k>>2];
                __nv_bfloat162 o0 = __floats2bfloat162_rn(tanhap(e4.x+d4.x), tanhap(e4.y+d4.y));
                __nv_bfloat162 o1 = __floats2bfloat162_rn(tanhap(e4.z+d4.z), tanhap(e4.w+d4.w));
                int kt = i*4 + (lane>>3);
                uint32_t addr = sA + (uint32_t)kt*8192 + (uint32_t)r*64 + colsw;
                uint32_t w0 = *(unsigned*)&o0, w1 = *(unsigned*)&o1;
                asm volatile("st.shared.v2.b32 [%0], {%1,%2};" :: "r"(addr), "r"(w0), "r"(w1));
            }
        }
    }

    // per-slot local rows (slot = mt*2 + half)
    int rows4[4];
    #pragma unroll
    for(int mt=0;mt<2;mt++)
        #pragma unroll
        for(int half=0;half<2;half++)
            rows4[mt*2+half] = warp_m*32 + mt*16 + half*8 + g;

    // ldmatrix swizzled offsets within a kt/buffer tile, both ks variants
    uint32_t aOff2[2][2];
    #pragma unroll
    for(int mt=0;mt<2;mt++){
        int r = warp_m*32 + mt*16 + (lane&7) + ((lane>>3)&1)*8;
        uint32_t off16 = ((lane>>4)&1)*16;
        #pragma unroll
        for(int ks=0;ks<2;ks++)
            aOff2[mt][ks] = (uint32_t)r*64 + ((off16 | (ks<<5)) ^ XBITS(r));
    }
    uint32_t bOff2[4][2];
    #pragma unroll
    for(int j=0;j<4;j++){
        int n = warp_n*64 + j*16 + (lane&7) + ((lane>>4)&1)*8;
        uint32_t off16 = ((lane>>3)&1)*16;
        #pragma unroll
        for(int ks=0;ks<2;ks++)
            bOff2[j][ks] = (uint32_t)n*64 + ((off16 | (ks<<5)) ^ XBITS(n));
    }

    float m4[4] = {-3.4e38f,-3.4e38f,-3.4e38f,-3.4e38f};
    float s4[4] = {0.f,0.f,0.f,0.f};
    float vt4[4] = {-3.4e38f,-3.4e38f,-3.4e38f,-3.4e38f};
    float v04[4] = {0.f,0.f,0.f,0.f};

    int brow = tid>>1, bc0 = (tid&1)*2;   // 128 rows x 2 x 16B per thread
    uint32_t bst0 = (uint32_t)brow*64 + (((uint32_t)bc0*16u)       ^ XBITS(brow));
    uint32_t bst1 = (uint32_t)brow*64 + (((uint32_t)bc0*16u + 16u) ^ XBITS(brow));
    #define LOADB(buf, stp) do{ \
        unsigned long long p = __cvta_generic_to_global( \
            (const char*)g_Wt + ((size_t)(((stp)>>4)*128 + brow))*1024 + ((stp)&15)*64 + bc0*16); \
        uint32_t dbase = sB + (uint32_t)(buf)*8192; \
        asm volatile("cp.async.cg.shared.global [%0], [%1], 16;" :: "r"(dbase + bst0), "l"(p)); \
        asm volatile("cp.async.cg.shared.global [%0], [%1], 16;" :: "r"(dbase + bst1), "l"(p+16)); \
    }while(0)

    // prefetch steps 0..3 (one commit group each)
    LOADB(0,0); asm volatile("cp.async.commit_group;");
    LOADB(1,1); asm volatile("cp.async.commit_group;");
    LOADB(2,2); asm volatile("cp.async.commit_group;");
    LOADB(3,3); asm volatile("cp.async.commit_group;");

    float acc[2][8][4];
    #pragma unroll
    for(int mt=0;mt<2;mt++)
        #pragma unroll
        for(int nt=0;nt<8;nt++)
            #pragma unroll
            for(int c=0;c<4;c++) acc[mt][nt][c]=0.f;

    for(int it=0; it<64; it++){
        int p0 = 2*it;
        if(p0+4 < 128){ LOADB((p0+4)&7, p0+4); }
        asm volatile("cp.async.commit_group;");
        if(p0+5 < 128){ LOADB((p0+5)&7, p0+5); }
        asm volatile("cp.async.commit_group;");
        asm volatile("cp.async.wait_group 4;");
        __syncthreads();

        #pragma unroll
        for(int half2=0; half2<2; half2++){
            int stp = p0 + half2;
            uint32_t aoff = sA + (uint32_t)(stp & 15)*8192;
            uint32_t boff = sB + (uint32_t)(stp & 7)*8192;
            #pragma unroll
            for(int ks=0;ks<2;ks++){
                uint32_t af[2][4];
                #pragma unroll
                for(int mt=0;mt<2;mt++)
                    asm volatile("ldmatrix.sync.aligned.m8n8.x4.shared.b16 {%0,%1,%2,%3}, [%4];"
                        : "=r"(af[mt][0]),"=r"(af[mt][1]),"=r"(af[mt][2]),"=r"(af[mt][3])
                        : "r"(aoff + aOff2[mt][ks]));
                uint32_t bf[8][2];
                #pragma unroll
                for(int j=0;j<4;j++){
                    uint32_t b0,b1,b2,b3;
                    asm volatile("ldmatrix.sync.aligned.m8n8.x4.shared.b16 {%0,%1,%2,%3}, [%4];"
                        : "=r"(b0),"=r"(b1),"=r"(b2),"=r"(b3)
                        : "r"(boff + bOff2[j][ks]));
                    bf[2*j][0]=b0; bf[2*j][1]=b1; bf[2*j+1][0]=b2; bf[2*j+1][1]=b3;
                }
                #pragma unroll
                for(int mt=0;mt<2;mt++)
                    #pragma unroll
                    for(int nt=0;nt<8;nt++)
                        asm volatile(
                            "mma.sync.aligned.m16n8k16.row.col.f32.bf16.bf16.f32 "
                            "{%0,%1,%2,%3}, {%4,%5,%6,%7}, {%8,%9}, {%0,%1,%2,%3};"
                            : "+f"(acc[mt][nt][0]), "+f"(acc[mt][nt][1]),
                              "+f"(acc[mt][nt][2]), "+f"(acc[mt][nt][3])
                            : "r"(af[mt][0]),"r"(af[mt][1]),"r"(af[mt][2]),"r"(af[mt][3]),
                              "r"(bf[nt][0]),"r"(bf[nt][1]));
            }
        }

        if(((p0+1) & 15) == 15){
            int nch = (p0+1) >> 4;
            int colw = nch*128 + warp_n*64;
            float br0[8], br1[8];
            #pragma unroll
            for(int nt=0;nt<8;nt++){
                br0[nt] = __ldg(&bout[colw + nt*8 + tg*2]);
                br1[nt] = __ldg(&bout[colw + nt*8 + tg*2 + 1]);
            }
            #pragma unroll
            for(int mt=0;mt<2;mt++){
                #pragma unroll
                for(int half=0;half<2;half++){
                    int slot = mt*2+half;
                    float v[16];
                    float cm = -3.4e38f;
                    #pragma unroll
                    for(int nt=0;nt<8;nt++){
                        v[nt*2]   = acc[mt][nt][half*2]   + br0[nt];
                        v[nt*2+1] = acc[mt][nt][half*2+1] + br1[nt];
                        cm = fmaxf(cm, fmaxf(v[nt*2], v[nt*2+1]));
                    }
                    float nm = fmaxf(m4[slot], cm);
                    float s = s4[slot]*__expf(m4[slot]-nm);
                    #pragma unroll
                    for(int nt=0;nt<8;nt++){
                        s += __expf(v[nt*2]-nm);
                        s += __expf(v[nt*2+1]-nm);
                        int c0 = colw + nt*8 + tg*2;
                        if(c0   == tgt) vt4[slot] = v[nt*2];
                        if(c0+1 == tgt) vt4[slot] = v[nt*2+1];
                    }
                    m4[slot] = nm; s4[slot] = s;
                    if(nch==0 && warp_n==0 && tg==0) v04[slot] = v[0];
                }
            }
            #pragma unroll
            for(int mt=0;mt<2;mt++)
                #pragma unroll
                for(int nt=0;nt<8;nt++)
                    #pragma unroll
                    for(int c=0;c<4;c++) acc[mt][nt][c]=0.f;
        }
    }
    #undef LOADB

    // ---- cross-quad + cross-warp_n combine ----
    #pragma unroll
    for(int slot=0;slot<4;slot++){
        #pragma unroll
        for(int o=1;o<4;o<<=1){
            float om = __shfl_xor_sync(0xffffffffu, m4[slot], o);
            float os = __shfl_xor_sync(0xffffffffu, s4[slot], o);
            float ov = __shfl_xor_sync(0xffffffffu, vt4[slot], o);
            float nm = fmaxf(m4[slot], om);
            s4[slot] = s4[slot]*__expf(m4[slot]-nm) + os*__expf(om-nm);
            m4[slot] = nm;
            vt4[slot] = fmaxf(vt4[slot], ov);
        }
        if(tg==0){
            int rl = rows4[slot];
            pm [warp_n*128 + rl] = m4[slot];
            ps [warp_n*128 + rl] = s4[slot];
            pvt[warp_n*128 + rl] = vt4[slot];
            if(warp_n==0) pv0[rl] = v04[slot];
        }
    }
    __syncthreads();
    if(tid < 128){
        int r = tid;
        int t = t0 + r;
        float m0 = pm[r], m1 = pm[128+r];
        float nm = fmaxf(m0, m1);
        float s = ps[r]*__expf(m0-nm) + ps[128+r]*__expf(m1-nm);
        float lse = nm + logf(s);
        g_blank[b*(Tn*U1) + t*U1 + u] = pv0[r] - lse;
        if(u < Un && u < tgt_lens[b]){
            float vt = fmaxf(pvt[r], pvt[128+r]);
            g_lbl[b*(Tn*Un) + t*Un + u] = vt - lse;
        }
    }
}

// ---------------- RNN-T forward DP: single-warp register wavefront ----------------
// Lane l owns u=2l (lo), u=2l+1 (hi); lane 31 also owns u=64 (ex).
// Diagonal n cells use only diagonal n-1 values: own regs + shfl_up of hi.
// No barriers in the 320-step loop.
#define DP_SMEM ((Tn*U1 + Tn*Un)*4)   // 132096 bytes
__device__ __forceinline__ float dp_cell(int n, int u, int uf, float pu, float pum1,
                                         const float* sb, const float* sl){
    int t = n - u;
    if(t < 0 || t >= Tn) return pu;          // not started / past end (unused)
    if(t == 0 && u == 0) return 0.f;
    if(t == 0) return (u <= uf) ? (pum1 + sl[u-1]) : NEGF;
    if(u == 0) return pu + sb[(t-1)*U1];
    if(u > uf) return NEGF;
    return laef(pu + sb[(t-1)*U1 + u], pum1 + sl[t*Un + (u-1)]);
}
__global__ void dp_kernel(const int* __restrict__ in_lens, const int* __restrict__ tgt_lens,
                          float* __restrict__ out){
    extern __shared__ float smf[];
    float* s_blank = smf;              // Tn*U1
    float* s_lbl   = smf + Tn*U1;      // Tn*Un
    int b = blockIdx.x;
    for(int i=threadIdx.x;i<Tn*U1;i+=blockDim.x) s_blank[i] = g_blank[b*Tn*U1 + i];
    for(int i=threadIdx.x;i<Tn*Un;i+=blockDim.x) s_lbl[i]   = g_lbl[b*Tn*Un + i];
    __syncthreads();
    if(threadIdx.x >= 32) return;      // warp 0 only from here (no more barriers)

    int l = threadIdx.x;
    int tl = in_lens[b]-1;
    int uf = tgt_lens[b];
    int lim = tl + uf;
    int u_lo = 2*l, u_hi = 2*l+1;
    float lo = NEGF, hi = NEGF, ex = NEGF;
    float fin = NEGF;
    for(int n=0;n<=lim;n++){
        float hprev = __shfl_up_sync(0xffffffffu, hi, 1);   // prev[u_lo-1]
        float olo = lo, ohi = hi, oex = ex;
        lo = dp_cell(n, u_lo, uf, olo, hprev, s_blank, s_lbl);
        hi = dp_cell(n, u_hi, uf, ohi, olo,   s_blank, s_lbl);
        if(l == 31) ex = dp_cell(n, 64, uf, oex, ohi, s_blank, s_lbl);
        // capture final cell alpha(tl, uf) + blank(tl, uf)
        if(n == tl + uf){
            float av = (uf == u_lo) ? lo : ((uf == u_hi) ? hi : ((uf == 64 && l == 31) ? ex : NEGF));
            if(uf == u_lo || uf == u_hi || (uf == 64 && l == 31))
                fin = av + s_blank[tl*U1 + uf];
        }
    }
    // one lane holds fin; others NEGF
    #pragma unroll
    for(int o=16;o>=1;o>>=1) fin = fmaxf(fin, __shfl_xor_sync(0xffffffffu, fin, o));
    if(l == 0) atomicAdd(out, -fin * (1.0f/Bn));
}

// ---------------- launch ----------------
extern "C" void kernel_launch(void* const* d_in, const int* in_sizes, int n_in,
                              void* d_out, int out_size){
    (void)in_sizes; (void)n_in; (void)out_size;
    const float* inputs  = (const float*)d_in[0];
    const float* W_enc   = (const float*)d_in[1];
    const float* emb     = (const float*)d_in[2];
    const float* W_jenc  = (const float*)d_in[3];
    const float* W_jdec  = (const float*)d_in[4];
    const float* b_j     = (const float*)d_in[5];
    const float* W_out   = (const float*)d_in[6];
    const float* b_out   = (const float*)d_in[7];
    const int*   targets = (const int*)d_in[8];
    const int*   in_lens = (const int*)d_in[9];
    const int*   tgt_lens= (const int*)d_in[10];
    float* out = (float*)d_out;

    cudaFuncSetAttribute(big_fused, cudaFuncAttributeMaxDynamicSharedMemorySize, BIG_SMEM);
    cudaFuncSetAttribute(dp_kernel, cudaFuncAttributeMaxDynamicSharedMemorySize, DP_SMEM);

    prep1<<<820, 256>>>(W_enc, W_jenc, emb, targets, W_out, out);
    prep2<<<656, 256>>>(inputs, W_jdec);
    big_fused<<<U1*Bn*2, 256, BIG_SMEM>>>(b_out, b_j, targets, in_lens, tgt_lens);
    dp_kernel<<<Bn, 128, DP_SMEM>>>(in_lens, tgt_lens, out);
}

// round 16
// speedup vs baseline: 1.0721x; 1.0714x over previous
#include <cuda_runtime.h>
#include <cuda_bf16.h>
#include <math.h>
#include <cstdint>

// Problem constants
#define Bn 4
#define Tn 256
#define Un 64
#define U1 65
#define Vn 1024
#define Fn 80
#define Hn 512
#define Jn 512
#define NROWS (Bn*Tn*U1)   // 66560 = 520*128
#define NEGF (-1e30f)

// ---------------- scratch (static __device__, allocation-free) ----------------
__device__ float g_Wcomb[Fn*Jn];                 // W_enc @ W_jenc (80x512)
__device__ float g_e  [Bn*Tn*Jn];                // (1024, 512)
__device__ float g_dec[Bn*U1*Hn];                // (260, 512)
__device__ float g_d  [Bn*U1*Jn];                // (260, 512)
__device__ __nv_bfloat16 g_Wt[(size_t)Vn*Jn];    // W_out^T bf16, [V][J] K-major
__device__ float g_blank[NROWS];                 // [b][t][u]
__device__ float g_lbl[Bn*Tn*Un];                // [b][t][u]

__device__ __forceinline__ uint32_t s2u(const void* p){
    uint32_t a;
    asm("{ .reg .u64 t; cvta.to.shared.u64 t, %1; cvt.u32.u64 %0, t; }" : "=r"(a) : "l"(p));
    return a;
}
__device__ __forceinline__ float tanhap(float x){
    float y; asm("tanh.approx.f32 %0, %1;" : "=f"(y) : "f"(x)); return y;
}
// fast logaddexp (MUFU-based; abs err ~1e-6)
__device__ __forceinline__ float laef(float a, float b){
    float m = fmaxf(a,b);
    float d = fabsf(a-b);
    return m + __logf(1.f + __expf(-d));
}
// per-row swizzle bits for 64B rows: flips 16B-chunk index (bits 4,5) by row bits 1,2
#define XBITS(r) ((((uint32_t)(r))&6u)<<3)

// ---------------- 32x32-tile SGEMM body (device fn, 256 threads) ----------------
__device__ void gemm32_dev(const float* __restrict__ A, const float* __restrict__ B,
                           float* __restrict__ C, int M, int N, int K, int bx, int by,
                           float* As /*[32*33]*/, float* Bs /*[32*33]*/){
    int tid = threadIdx.x;
    int tx = tid & 15, ty = tid >> 4;
    int rowBase = by*32, colBase = bx*32;
    float acc[2][2] = {};
    for(int k0=0;k0<K;k0+=32){
        #pragma unroll
        for(int i=0;i<4;i++){
            int idx = i*256+tid;
            int m = idx>>5, k = idx&31;
            int gm = rowBase+m, gk = k0+k;
            As[m*33+k] = (gm<M && gk<K) ? A[(size_t)gm*K+gk] : 0.f;
            int kb = idx>>5, n = idx&31;
            int gkb = k0+kb, gn = colBase+n;
            Bs[kb*33+n] = (gkb<K && gn<N) ? B[(size_t)gkb*N+gn] : 0.f;
        }
        __syncthreads();
        #pragma unroll
        for(int kk=0;kk<32;kk++){
            float a0 = As[(ty*2+0)*33+kk], a1 = As[(ty*2+1)*33+kk];
            float b0 = Bs[kk*33+tx*2+0], b1 = Bs[kk*33+tx*2+1];
            acc[0][0] = fmaf(a0,b0,acc[0][0]);
            acc[0][1] = fmaf(a0,b1,acc[0][1]);
            acc[1][0] = fmaf(a1,b0,acc[1][0]);
            acc[1][1] = fmaf(a1,b1,acc[1][1]);
        }
        __syncthreads();
    }
    #pragma unroll
    for(int i=0;i<2;i++){
        int gm = rowBase+ty*2+i;
        if(gm<M)
            #pragma unroll
            for(int j=0;j<2;j++){
                int gn = colBase+tx*2+j;
                if(gn<N) C[(size_t)gm*N+gn]=acc[i][j];
            }
    }
}

// ---------------- prep1: Wcomb GEMM + gather_dec + wtrans in one launch ----------------
__global__ __launch_bounds__(256) void prep1(const float* __restrict__ W_enc,
                                             const float* __restrict__ W_jenc,
                                             const float* __restrict__ emb,
                                             const int* __restrict__ targets,
                                             const float* __restrict__ W_out,
                                             float* __restrict__ out){
    __shared__ float sh[2*32*33];
    int bid = blockIdx.x, tid = threadIdx.x;
    if(bid < 48){
        gemm32_dev(W_enc, W_jenc, g_Wcomb, Fn, Jn, Hn, bid&15, bid>>4, sh, sh+32*33);
    } else if(bid < 308){
        if(bid==48 && tid==0) out[0] = 0.f;
        int row = bid - 48;                 // 0..259 = b*65+u
        int b = row / U1, u = row - b*U1;
        int tok = (u==0) ? 0 : targets[b*Un + (u-1)];
        const float* src = emb + (size_t)tok*Hn;
        float* dst = g_dec + (size_t)row*Hn;
        #pragma unroll
        for(int i=0;i<2;i++) dst[tid + i*256] = src[tid + i*256];
    } else {
        int idx = bid - 308;                // 512 tiles: 32 v-tiles x 16 j-tiles
        int v0 = (idx & 31)*32, j0 = (idx >> 5)*32;
        float (*t)[33] = (float(*)[33])sh;
        int tx = tid & 31, ty = tid >> 5;   // 32 x 8
        for(int i=ty;i<32;i+=8)
            t[i][tx] = W_out[(size_t)(j0+i)*Vn + v0 + tx];
        __syncthreads();
        for(int i=ty;i<32;i+=8)
            g_Wt[(size_t)(v0+i)*Jn + j0 + tx] = __float2bfloat16(t[tx][i]);
    }
}

// ---------------- prep2: e-GEMM + d-GEMM in one launch ----------------
__global__ __launch_bounds__(256) void prep2(const float* __restrict__ inputs,
                                             const float* __restrict__ W_jdec){
    __shared__ float sh[2*32*33];
    int bid = blockIdx.x;
    if(bid < 512){
        gemm32_dev(inputs, g_Wcomb, g_e, Bn*Tn, Jn, Fn, bid&15, bid>>4, sh, sh+32*33);
    } else {
        int idx = bid - 512;                // 144: 9 row x 16 col tiles
        gemm32_dev(g_dec, W_jdec, g_d, Bn*U1, Jn, Hn, idx&15, idx>>4, sh, sh+32*33);
    }
}

// ================= fused joint kernel (u-major tiling + dead-CTA skip) =================
// Grid 520 = 65 u x 4 b x 2 t-halves. CTA: 128 t-rows (single u,b) x 1024 cols.
// Early exit if u > tgt_lens[b] or t0 >= in_lens[b]  (rows never read by DP).
#define ABYTES (16*128*64)            // 131072
#define BRING  (8*128*64)             // 65536
#define SOFFB  (ABYTES + BRING)       // 196608
#define DBOFF  (SOFFB + 3584)         // d+bj row (512 f32)
#define BIG_SMEM (DBOFF + 2048)       // 202240
__global__ void __launch_bounds__(256) big_fused(const float* __restrict__ bout,
                                                 const float* __restrict__ bj,
                                                 const int* __restrict__ targets,
                                                 const int* __restrict__ in_lens,
                                                 const int* __restrict__ tgt_lens){
    int u    = blockIdx.x >> 3;          // 0..64
    int sub  = blockIdx.x & 7;
    int b    = sub >> 1;                 // 0..3
    int t0   = (sub & 1) * 128;
    if(u > tgt_lens[b]) return;          // dead column band
    if(t0 >= in_lens[b]) return;         // dead time band

    extern __shared__ char sm[];
    uint32_t sA = s2u(sm);
    uint32_t sB = sA + ABYTES;
    float* pm  = (float*)(sm + SOFFB);          // [2][128]
    float* ps  = pm + 256;                      // [2][128]
    float* pvt = ps + 256;                      // [2][128]
    float* pv0 = pvt + 256;                     // [128]
    float* db  = (float*)(sm + DBOFF);          // d_u + bj (512)

    int tid = threadIdx.x, wid = tid>>5, lane = tid&31;
    int g = lane>>2, tg = lane&3;
    int warp_m = wid & 3, warp_n = wid >> 2;    // 4 x 2
    int tgt = (u < Un) ? targets[b*Un + u] : -1;

    // ---- stage d_u + bj ----
    {
        const float* drow = g_d + (size_t)(b*U1+u)*Jn;
        #pragma unroll
        for(int i=0;i<2;i++){
            int k = tid + i*256;
            db[k] = drow[k] + bj[k];
        }
    }
    __syncthreads();

    // ---- prologue: H = tanh(e[bt] + db) -> bf16 into A smem; warp owns 16 rows ----
    {
        int r0 = wid*16;
        #pragma unroll
        for(int rr=0;rr<16;rr++){
            int r = r0 + rr;
            int bt = b*Tn + t0 + r;
            const float4* ep = (const float4*)(g_e + (size_t)bt*Jn);
            const float4* dp = (const float4*)db;
            uint32_t xr = XBITS(r);
            uint32_t colsw = (((uint32_t)(lane&7))*8u) ^ xr;
            #pragma unroll
            for(int i=0;i<4;i++){
                int k = i*128 + lane*4;
                float4 e4 = ep[k>>2], d4 = dp[k>>2];
                __nv_bfloat162 o0 = __floats2bfloat162_rn(tanhap(e4.x+d4.x), tanhap(e4.y+d4.y));
                __nv_bfloat162 o1 = __floats2bfloat162_rn(tanhap(e4.z+d4.z), tanhap(e4.w+d4.w));
                int kt = i*4 + (lane>>3);
                uint32_t addr = sA + (uint32_t)kt*8192 + (uint32_t)r*64 + colsw;
                uint32_t w0 = *(unsigned*)&o0, w1 = *(unsigned*)&o1;
                asm volatile("st.shared.v2.b32 [%0], {%1,%2};" :: "r"(addr), "r"(w0), "r"(w1));
            }
        }
    }

    // per-slot local rows (slot = mt*2 + half)
    int rows4[4];
    #pragma unroll
    for(int mt=0;mt<2;mt++)
        #pragma unroll
        for(int half=0;half<2;half++)
            rows4[mt*2+half] = warp_m*32 + mt*16 + half*8 + g;

    // ldmatrix swizzled offsets within a kt/buffer tile, both ks variants
    uint32_t aOff2[2][2];
    #pragma unroll
    for(int mt=0;mt<2;mt++){
        int r = warp_m*32 + mt*16 + (lane&7) + ((lane>>3)&1)*8;
        uint32_t off16 = ((lane>>4)&1)*16;
        #pragma unroll
        for(int ks=0;ks<2;ks++)
            aOff2[mt][ks] = (uint32_t)r*64 + ((off16 | (ks<<5)) ^ XBITS(r));
    }
    uint32_t bOff2[4][2];
    #pragma unroll
    for(int j=0;j<4;j++){
        int n = warp_n*64 + j*16 + (lane&7) + ((lane>>4)&1)*8;
        uint32_t off16 = ((lane>>3)&1)*16;
        #pragma unroll
        for(int ks=0;ks<2;ks++)
            bOff2[j][ks] = (uint32_t)n*64 + ((off16 | (ks<<5)) ^ XBITS(n));
    }

    float m4[4] = {-3.4e38f,-3.4e38f,-3.4e38f,-3.4e38f};
    float s4[4] = {0.f,0.f,0.f,0.f};
    float vt4[4] = {-3.4e38f,-3.4e38f,-3.4e38f,-3.4e38f};
    float v04[4] = {0.f,0.f,0.f,0.f};

    int brow = tid>>1, bc0 = (tid&1)*2;   // 128 rows x 2 x 16B per thread
    uint32_t bst0 = (uint32_t)brow*64 + (((uint32_t)bc0*16u)       ^ XBITS(brow));
    uint32_t bst1 = (uint32_t)brow*64 + (((uint32_t)bc0*16u + 16u) ^ XBITS(brow));
    #define LOADB(buf, stp) do{ \
        unsigned long long p = __cvta_generic_to_global( \
            (const char*)g_Wt + ((size_t)(((stp)>>4)*128 + brow))*1024 + ((stp)&15)*64 + bc0*16); \
        uint32_t dbase = sB + (uint32_t)(buf)*8192; \
        asm volatile("cp.async.cg.shared.global [%0], [%1], 16;" :: "r"(dbase + bst0), "l"(p)); \
        asm volatile("cp.async.cg.shared.global [%0], [%1], 16;" :: "r"(dbase + bst1), "l"(p+16)); \
    }while(0)

    // prefetch steps 0..3 (one commit group each)
    LOADB(0,0); asm volatile("cp.async.commit_group;");
    LOADB(1,1); asm volatile("cp.async.commit_group;");
    LOADB(2,2); asm volatile("cp.async.commit_group;");
    LOADB(3,3); asm volatile("cp.async.commit_group;");

    float acc[2][8][4];
    #pragma unroll
    for(int mt=0;mt<2;mt++)
        #pragma unroll
        for(int nt=0;nt<8;nt++)
            #pragma unroll
            for(int c=0;c<4;c++) acc[mt][nt][c]=0.f;

    for(int it=0; it<64; it++){
        int p0 = 2*it;
        if(p0+4 < 128){ LOADB((p0+4)&7, p0+4); }
        asm volatile("cp.async.commit_group;");
        if(p0+5 < 128){ LOADB((p0+5)&7, p0+5); }
        asm volatile("cp.async.commit_group;");
        asm volatile("cp.async.wait_group 4;");
        __syncthreads();

        #pragma unroll
        for(int half2=0; half2<2; half2++){
            int stp = p0 + half2;
            uint32_t aoff = sA + (uint32_t)(stp & 15)*8192;
            uint32_t boff = sB + (uint32_t)(stp & 7)*8192;
            #pragma unroll
            for(int ks=0;ks<2;ks++){
                uint32_t af[2][4];
                #pragma unroll
                for(int mt=0;mt<2;mt++)
                    asm volatile("ldmatrix.sync.aligned.m8n8.x4.shared.b16 {%0,%1,%2,%3}, [%4];"
                        : "=r"(af[mt][0]),"=r"(af[mt][1]),"=r"(af[mt][2]),"=r"(af[mt][3])
                        : "r"(aoff + aOff2[mt][ks]));
                uint32_t bf[8][2];
                #pragma unroll
                for(int j=0;j<4;j++){
                    uint32_t b0,b1,b2,b3;
                    asm volatile("ldmatrix.sync.aligned.m8n8.x4.shared.b16 {%0,%1,%2,%3}, [%4];"
                        : "=r"(b0),"=r"(b1),"=r"(b2),"=r"(b3)
                        : "r"(boff + bOff2[j][ks]));
                    bf[2*j][0]=b0; bf[2*j][1]=b1; bf[2*j+1][0]=b2; bf[2*j+1][1]=b3;
                }
                #pragma unroll
                for(int mt=0;mt<2;mt++)
                    #pragma unroll
                    for(int nt=0;nt<8;nt++)
                        asm volatile(
                            "mma.sync.aligned.m16n8k16.row.col.f32.bf16.bf16.f32 "
                            "{%0,%1,%2,%3}, {%4,%5,%6,%7}, {%8,%9}, {%0,%1,%2,%3};"
                            : "+f"(acc[mt][nt][0]), "+f"(acc[mt][nt][1]),
                              "+f"(acc[mt][nt][2]), "+f"(acc[mt][nt][3])
                            : "r"(af[mt][0]),"r"(af[mt][1]),"r"(af[mt][2]),"r"(af[mt][3]),
                              "r"(bf[nt][0]),"r"(bf[nt][1]));
            }
        }

        if(((p0+1) & 15) == 15){
            int nch = (p0+1) >> 4;
            int colw = nch*128 + warp_n*64;
            float br0[8], br1[8];
            #pragma unroll
            for(int nt=0;nt<8;nt++){
                br0[nt] = __ldg(&bout[colw + nt*8 + tg*2]);
                br1[nt] = __ldg(&bout[colw + nt*8 + tg*2 + 1]);
            }
            #pragma unroll
            for(int mt=0;mt<2;mt++){
                #pragma unroll
                for(int half=0;half<2;half++){
                    int slot = mt*2+half;
                    float v[16];
                    float cm = -3.4e38f;
                    #pragma unroll
                    for(int nt=0;nt<8;nt++){
                        v[nt*2]   = acc[mt][nt][half*2]   + br0[nt];
                        v[nt*2+1] = acc[mt][nt][half*2+1] + br1[nt];
                        cm = fmaxf(cm, fmaxf(v[nt*2], v[nt*2+1]));
                    }
                    float nm = fmaxf(m4[slot], cm);
                    float s = s4[slot]*__expf(m4[slot]-nm);
                    #pragma unroll
                    for(int nt=0;nt<8;nt++){
                        s += __expf(v[nt*2]-nm);
                        s += __expf(v[nt*2+1]-nm);
                        int c0 = colw + nt*8 + tg*2;
                        if(c0   == tgt) vt4[slot] = v[nt*2];
                        if(c0+1 == tgt) vt4[slot] = v[nt*2+1];
                    }
                    m4[slot] = nm; s4[slot] = s;
                    if(nch==0 && warp_n==0 && tg==0) v04[slot] = v[0];
                }
            }
            #pragma unroll
            for(int mt=0;mt<2;mt++)
                #pragma unroll
                for(int nt=0;nt<8;nt++)
                    #pragma unroll
                    for(int c=0;c<4;c++) acc[mt][nt][c]=0.f;
        }
    }
    #undef LOADB

    // ---- cross-quad + cross-warp_n combine ----
    #pragma unroll
    for(int slot=0;slot<4;slot++){
        #pragma unroll
        for(int o=1;o<4;o<<=1){
            float om = __shfl_xor_sync(0xffffffffu, m4[slot], o);
            float os = __shfl_xor_sync(0xffffffffu, s4[slot], o);
            float ov = __shfl_xor_sync(0xffffffffu, vt4[slot], o);
            float nm = fmaxf(m4[slot], om);
            s4[slot] = s4[slot]*__expf(m4[slot]-nm) + os*__expf(om-nm);
            m4[slot] = nm;
            vt4[slot] = fmaxf(vt4[slot], ov);
        }
        if(tg==0){
            int rl = rows4[slot];
            pm [warp_n*128 + rl] = m4[slot];
            ps [warp_n*128 + rl] = s4[slot];
            pvt[warp_n*128 + rl] = vt4[slot];
            if(warp_n==0) pv0[rl] = v04[slot];
        }
    }
    __syncthreads();
    if(tid < 128){
        int r = tid;
        int t = t0 + r;
        float m0 = pm[r], m1 = pm[128+r];
        float nm = fmaxf(m0, m1);
        float s = ps[r]*__expf(m0-nm) + ps[128+r]*__expf(m1-nm);
        float lse = nm + logf(s);
        g_blank[b*(Tn*U1) + t*U1 + u] = pv0[r] - lse;
        if(u < Un && u < tgt_lens[b]){
            float vt = fmaxf(pvt[r], pvt[128+r]);
            g_lbl[b*(Tn*Un) + t*Un + u] = vt - lse;
        }
    }
}

// ---------------- RNN-T forward DP: 1 block, warp w = batch w ----------------
// Lane l owns u=2l (lo), u=2l+1 (hi); lane 31 also owns u=64 (ex).
// No barriers; tables read from L2 via __ldg with 4-diagonal register prefetch.
__device__ __forceinline__ float dp_cellv(int n, int u, int uf, float pu, float pum1,
                                          float bl, float lb){
    int t = n - u;
    if(t < 0 || t >= Tn) return pu;
    if(t == 0 && u == 0) return 0.f;
    if(t == 0) return (u <= uf) ? (pum1 + lb) : NEGF;
    if(u == 0) return pu + bl;
    if(u > uf) return NEGF;
    return laef(pu + bl, pum1 + lb);
}
__global__ void __launch_bounds__(128) dp_kernel(const int* __restrict__ in_lens,
                                                 const int* __restrict__ tgt_lens,
                                                 float* __restrict__ out){
    int w = threadIdx.x >> 5;          // batch
    int l = threadIdx.x & 31;
    const float* Bp = g_blank + w*(Tn*U1);
    const float* Lp = g_lbl   + w*(Tn*Un);
    int tl = in_lens[w]-1;
    int uf = tgt_lens[w];
    int lim = tl + uf;
    int u_lo = 2*l, u_hi = 2*l+1;

    // clamped-address loader for diagonal n (bl = blank[t-1][u], lb = lbl[t][u-1])
    #define LDQ(n, u, blv, lbv) do{ \
        int t_ = (n) - (u); \
        int ta_ = min(max(t_-1, 0), Tn-1); \
        int tb_ = min(max(t_,   0), Tn-1); \
        int um_ = max((u)-1, 0); \
        int uc_ = min((u), Un-1); \
        blv = __ldg(Bp + ta_*U1 + (u)); \
        lbv = __ldg(Lp + tb_*Un + min(um_, Un-1)); (void)uc_; \
    }while(0)

    float qb_lo[4], ql_lo[4], qb_hi[4], ql_hi[4], qb_ex[4], ql_ex[4];
    #pragma unroll
    for(int i=0;i<4;i++){
        LDQ(i, u_lo, qb_lo[i], ql_lo[i]);
        LDQ(i, u_hi, qb_hi[i], ql_hi[i]);
        LDQ(i, 64,   qb_ex[i], ql_ex[i]);
    }

    float lo = NEGF, hi = NEGF, ex = NEGF, fin = NEGF;
    for(int base=0; base<=lim; base+=4){
        float nb_lo[4], nl_lo[4], nb_hi[4], nl_hi[4], nb_ex[4], nl_ex[4];
        #pragma unroll
        for(int i=0;i<4;i++){
            int n2 = base + 4 + i;
            LDQ(n2, u_lo, nb_lo[i], nl_lo[i]);
            LDQ(n2, u_hi, nb_hi[i], nl_hi[i]);
            LDQ(n2, 64,   nb_ex[i], nl_ex[i]);
        }
        #pragma unroll
        for(int i=0;i<4;i++){
            int n = base + i;
            if(n <= lim){
                float hprev = __shfl_up_sync(0xffffffffu, hi, 1);
                float olo = lo, ohi = hi, oex = ex;
                lo = dp_cellv(n, u_lo, uf, olo, hprev, qb_lo[i], ql_lo[i]);
                hi = dp_cellv(n, u_hi, uf, ohi, olo,   qb_hi[i], ql_hi[i]);
                if(l == 31) ex = dp_cellv(n, 64, uf, oex, ohi, qb_ex[i], ql_ex[i]);
                if(n == lim){
                    bool mine = (uf == u_lo) || (uf == u_hi) || (uf == 64 && l == 31);
                    if(mine){
                        float av = (uf == u_lo) ? lo : ((uf == u_hi) ? hi : ex);
                        fin = av + __ldg(Bp + tl*U1 + uf);
                    }
                }
            }
        }
        #pragma unroll
        for(int i=0;i<4;i++){
            qb_lo[i]=nb_lo[i]; ql_lo[i]=nl_lo[i];
            qb_hi[i]=nb_hi[i]; ql_hi[i]=nl_hi[i];
            qb_ex[i]=nb_ex[i]; ql_ex[i]=nl_ex[i];
        }
    }
    #undef LDQ
    // one lane per warp holds fin
    #pragma unroll
    for(int o=16;o>=1;o>>=1) fin = fmaxf(fin, __shfl_xor_sync(0xffffffffu, fin, o));
    if(l == 0) atomicAdd(out, -fin * (1.0f/Bn));
}

// ---------------- launch ----------------
extern "C" void kernel_launch(void* const* d_in, const int* in_sizes, int n_in,
                              void* d_out, int out_size){
    (void)in_sizes; (void)n_in; (void)out_size;
    const float* inputs  = (const float*)d_in[0];
    const float* W_enc   = (const float*)d_in[1];
    const float* emb     = (const float*)d_in[2];
    const float* W_jenc  = (const float*)d_in[3];
    const float* W_jdec  = (const float*)d_in[4];
    const float* b_j     = (const float*)d_in[5];
    const float* W_out   = (const float*)d_in[6];
    const float* b_out   = (const float*)d_in[7];
    const int*   targets = (const int*)d_in[8];
    const int*   in_lens = (const int*)d_in[9];
    const int*   tgt_lens= (const int*)d_in[10];
    float* out = (float*)d_out;

    cudaFuncSetAttribute(big_fused, cudaFuncAttributeMaxDynamicSharedMemorySize, BIG_SMEM);

    prep1<<<820, 256>>>(W_enc, W_jenc, emb, targets, W_out, out);
    prep2<<<656, 256>>>(inputs, W_jdec);
    big_fused<<<U1*Bn*2, 256, BIG_SMEM>>>(b_out, b_j, targets, in_lens, tgt_lens);
    dp_kernel<<<1, 128>>>(in_lens, tgt_lens, out);
}